// round 2
// baseline (speedup 1.0000x reference)
#include <cuda_runtime.h>
#include <math.h>
#include <stdint.h>

#define N_NODES 10000
#define N_EDGES 160000
#define N_GRAPHS 64
#define T_TOW 5
#define FI 75
#define FO 15
#define N_LAYERS 4
#define MSG_DIM 375        // T*FI
#define MIN_DIM 225        // 3*FI
#define OUT_DIM 975        // 13*FI
#define HC_K 4875          // T*975
#define AVG_DEG_LOG 2.8332133440562162f

// ---------------- scratch -------------------------------------------------
__device__ float d_h[N_NODES * FI];
__device__ float d_hc[N_NODES * FI];
__device__ float d_msgs[N_EDGES * MSG_DIM];        // msgs in CSR edge order
__device__ float d_agg[N_NODES * T_TOW * 4 * FI];  // [N,T,300]
__device__ float d_outbuf[N_NODES * HC_K];         // [N,4875]
__device__ float d_Wt[MIN_DIM * MSG_DIM];          // pre_W[l] transposed [225,375]
__device__ float d_fusedW[HC_K * FI];              // [4875,75]
__device__ float d_bias2[FI];
__device__ float d_enctab[16 * FI];                // 16 (a0,a1) combos
__device__ int   d_cnt[N_NODES];
__device__ int   d_rowstart[N_NODES + 1];
__device__ int   d_cursor[N_NODES];
__device__ int   d_src_csr[N_EDGES];
__device__ int   d_dst_csr[N_EDGES];
__device__ int   d_combo_csr[N_EDGES];
__device__ float d_bnsum[FI];
__device__ float d_bnsq[FI];
__device__ float d_pool[N_GRAPHS * FI];

__device__ __forceinline__ float tf32r(float v) {
    uint32_t o;
    asm("cvt.rna.tf32.f32 %0, %1;" : "=r"(o) : "f"(v));
    return __uint_as_float(o);
}

__device__ __forceinline__ void mma_tf32(float* c, const uint32_t* a, const uint32_t* b) {
    asm volatile(
        "mma.sync.aligned.m16n8k8.row.col.f32.tf32.tf32.f32 "
        "{%0,%1,%2,%3}, {%4,%5,%6,%7}, {%8,%9}, {%0,%1,%2,%3};"
        : "+f"(c[0]), "+f"(c[1]), "+f"(c[2]), "+f"(c[3])
        : "r"(a[0]), "r"(a[1]), "r"(a[2]), "r"(a[3]), "r"(b[0]), "r"(b[1]));
}

// ---------------- h0 -------------------------------------------------------
__global__ void k_h0(const int* __restrict__ x, const float* __restrict__ node_emb,
                     const float* __restrict__ W, const float* __restrict__ b) {
    int idx = blockIdx.x * blockDim.x + threadIdx.x;
    if (idx >= N_NODES * FI) return;
    int n = idx / FI, f = idx % FI;
    int i0 = x[n * 2 + 0], i1 = x[n * 2 + 1];
    const float* e0 = node_emb + i0 * FI;
    const float* e1 = node_emb + i1 * FI;
    float acc = b[f];
    #pragma unroll 5
    for (int c = 0; c < FI; c++) acc += e0[c] * W[c * FI + f];
    #pragma unroll 5
    for (int c = 0; c < FI; c++) acc += e1[c] * W[(FI + c) * FI + f];
    d_h[idx] = acc;
}

// ---------------- CSR build ------------------------------------------------
__global__ void k_zero_cnt() {
    int i = blockIdx.x * blockDim.x + threadIdx.x;
    if (i < N_NODES) d_cnt[i] = 0;
}

__global__ void k_count(const int* __restrict__ edge_index) {
    int e = blockIdx.x * blockDim.x + threadIdx.x;
    if (e >= N_EDGES) return;
    atomicAdd(&d_cnt[edge_index[N_EDGES + e]], 1);
}

__global__ void k_scan() {
    __shared__ int ssum[1024];
    int tid = threadIdx.x;
    const int ITEMS = 10;
    int base = tid * ITEMS;
    int local[ITEMS];
    int s = 0;
    #pragma unroll
    for (int i = 0; i < ITEMS; i++) {
        int g = base + i;
        int v = (g < N_NODES) ? d_cnt[g] : 0;
        local[i] = s;
        s += v;
    }
    ssum[tid] = s;
    __syncthreads();
    for (int off = 1; off < 1024; off <<= 1) {
        int v = (tid >= off) ? ssum[tid - off] : 0;
        __syncthreads();
        ssum[tid] += v;
        __syncthreads();
    }
    int excl = (tid == 0) ? 0 : ssum[tid - 1];
    #pragma unroll
    for (int i = 0; i < ITEMS; i++) {
        int g = base + i;
        if (g < N_NODES) {
            int rs = excl + local[i];
            d_rowstart[g] = rs;
            d_cursor[g]   = rs;
        }
    }
    if (tid == 0) d_rowstart[N_NODES] = ssum[1023];
}

__global__ void k_fill(const int* __restrict__ edge_index, const int* __restrict__ edge_attr) {
    int e = blockIdx.x * blockDim.x + threadIdx.x;
    if (e >= N_EDGES) return;
    int dst = edge_index[N_EDGES + e];
    int pos = atomicAdd(&d_cursor[dst], 1);
    d_src_csr[pos]  = edge_index[e];
    d_dst_csr[pos]  = dst;
    d_combo_csr[pos] = edge_attr[e * 2] * 4 + edge_attr[e * 2 + 1];
}

// ---------------- per-layer weight prep -------------------------------------
__global__ void k_enctab(const float* __restrict__ edge_emb,
                         const float* __restrict__ encW, const float* __restrict__ encb) {
    int idx = blockIdx.x * blockDim.x + threadIdx.x;
    if (idx >= 16 * FI) return;
    int combo = idx / FI, f = idx % FI;
    int a0 = combo >> 2, a1 = combo & 3;
    const float* e0 = edge_emb + a0 * 25;
    const float* e1 = edge_emb + a1 * 25;
    float acc = encb[f];
    #pragma unroll 5
    for (int q = 0; q < 25; q++) acc += e0[q] * encW[q * FI + f];
    #pragma unroll 5
    for (int q = 0; q < 25; q++) acc += e1[q] * encW[(25 + q) * FI + f];
    d_enctab[idx] = acc;
}

__global__ void k_transpose(const float* __restrict__ preW) {
    int idx = blockIdx.x * blockDim.x + threadIdx.x;
    if (idx >= MIN_DIM * MSG_DIM) return;
    int c = idx / MSG_DIM, j = idx % MSG_DIM;
    int t = j / FI, f = j % FI;
    d_Wt[idx] = preW[(t * MIN_DIM + c) * FI + f];
}

// fusedW[t*975+c][j] = sum_f postW[t][c][f] * linW[t*15+f][j]
__global__ void k_fusew(const float* __restrict__ postW, const float* __restrict__ linW) {
    int idx = blockIdx.x * blockDim.x + threadIdx.x;
    if (idx >= HC_K * FI) return;
    int k = idx / FI, j = idx % FI;
    int t = k / OUT_DIM, c = k % OUT_DIM;
    const float* pw = postW + ((size_t)t * OUT_DIM + c) * FO;
    const float* lw = linW + t * FO * FI + j;
    float acc = 0.f;
    #pragma unroll
    for (int f = 0; f < FO; f++) acc += pw[f] * lw[f * FI];
    d_fusedW[idx] = acc;
}

__global__ void k_bias2(const float* __restrict__ postb, const float* __restrict__ linW,
                        const float* __restrict__ linb) {
    int j = threadIdx.x;
    if (j >= FI) return;
    float acc = linb[j];
    #pragma unroll 5
    for (int q = 0; q < T_TOW * FO; q++) acc += postb[q] * linW[q * FI + j];
    d_bias2[j] = acc;
}

__global__ void k_bnzero() {
    int i = threadIdx.x;
    if (i < FI) { d_bnsum[i] = 0.f; d_bnsq[i] = 0.f; }
}

// ---------------- msgs GEMM (tf32 mma, fused gather, CSR row order) ---------
// C[160000,375] = A[160000,225] @ Wt[225,375] + bias
__global__ void __launch_bounds__(256) k_gemm_msg(const float* __restrict__ bias) {
    const int BM = 128, BN = 64, BK = 64;
    __shared__ float As[BM][BK + 4];   // stride 68
    __shared__ float Bs[BK][BN + 8];   // stride 72
    int bx = blockIdx.x, by = blockIdx.y;
    int tid = threadIdx.x;
    int row0 = by * BM, col0 = bx * BN;
    int lane = tid & 31, warp = tid >> 5;
    int wm = (warp >> 1) * 32, wn = (warp & 1) * 32;
    int g = lane >> 2, tc = lane & 3;

    float acc[2][4][4];
    #pragma unroll
    for (int i = 0; i < 2; i++)
        #pragma unroll
        for (int j = 0; j < 4; j++)
            #pragma unroll
            for (int q = 0; q < 4; q++) acc[i][j][q] = 0.f;

    // A fill: one row per thread pair
    int arow = tid >> 1;
    int ac0 = (tid & 1) * 32;
    int grow = row0 + arow;
    int dst = d_dst_csr[grow], src = d_src_csr[grow], combo = d_combo_csr[grow];
    const float* hd = d_h + dst * FI;
    const float* hs = d_h + src * FI;
    const float* tb = d_enctab + combo * FI;
    int bkr = tid >> 2, bc0 = (tid & 3) * 16;

    for (int k0 = 0; k0 < 256; k0 += BK) {
        #pragma unroll
        for (int c = 0; c < 32; c++) {
            int gc = k0 + ac0 + c;
            float v = 0.f;
            if (gc < FI) v = hd[gc];
            else if (gc < 2 * FI) v = hs[gc - FI];
            else if (gc < MIN_DIM) v = tb[gc - 2 * FI];
            As[arow][ac0 + c] = tf32r(v);
        }
        #pragma unroll
        for (int c = 0; c < 16; c++) {
            int kk = k0 + bkr, j = col0 + bc0 + c;
            float v = (kk < MIN_DIM && j < MSG_DIM) ? d_Wt[kk * MSG_DIM + j] : 0.f;
            Bs[bkr][bc0 + c] = tf32r(v);
        }
        __syncthreads();
        #pragma unroll
        for (int kk = 0; kk < BK; kk += 8) {
            uint32_t a[2][4], b[4][2];
            #pragma unroll
            for (int i = 0; i < 2; i++) {
                int m = wm + i * 16 + g;
                a[i][0] = __float_as_uint(As[m][kk + tc]);
                a[i][1] = __float_as_uint(As[m + 8][kk + tc]);
                a[i][2] = __float_as_uint(As[m][kk + tc + 4]);
                a[i][3] = __float_as_uint(As[m + 8][kk + tc + 4]);
            }
            #pragma unroll
            for (int j = 0; j < 4; j++) {
                int n = wn + j * 8 + g;
                b[j][0] = __float_as_uint(Bs[kk + tc][n]);
                b[j][1] = __float_as_uint(Bs[kk + tc + 4][n]);
            }
            #pragma unroll
            for (int i = 0; i < 2; i++)
                #pragma unroll
                for (int j = 0; j < 4; j++) mma_tf32(acc[i][j], a[i], b[j]);
        }
        __syncthreads();
    }
    #pragma unroll
    for (int i = 0; i < 2; i++) {
        int r = row0 + wm + i * 16 + g;
        #pragma unroll
        for (int j = 0; j < 4; j++) {
            int cb = col0 + wn + j * 8 + 2 * tc;
            if (cb < MSG_DIM) {
                d_msgs[(size_t)r * MSG_DIM + cb] = acc[i][j][0] + bias[cb];
                d_msgs[(size_t)(r + 8) * MSG_DIM + cb] = acc[i][j][2] + bias[cb];
                if (cb + 1 < MSG_DIM) {
                    d_msgs[(size_t)r * MSG_DIM + cb + 1] = acc[i][j][1] + bias[cb + 1];
                    d_msgs[(size_t)(r + 8) * MSG_DIM + cb + 1] = acc[i][j][3] + bias[cb + 1];
                }
            }
        }
    }
}

// ---------------- segment reduce (msgs in CSR order -> contiguous) ----------
__global__ void k_agg() {
    int n = blockIdx.x;
    int j = threadIdx.x;
    if (j >= MSG_DIM) return;
    int s0 = d_rowstart[n], s1 = d_rowstart[n + 1];
    float s = 0.f, sq = 0.f, mn = 3.4e38f, mx = -3.4e38f;
    for (int i = s0; i < s1; i++) {
        float v = d_msgs[(size_t)i * MSG_DIM + j];
        s += v; sq += v * v;
        mn = fminf(mn, v); mx = fmaxf(mx, v);
    }
    float cnt = (float)(s1 - s0);
    float deg = fmaxf(cnt, 1.f);
    float mean = s / deg;
    float var = sq / deg - mean * mean;
    if (var < 0.f) var = 0.f;
    float stdv = sqrtf(var + 1e-5f);
    if (s1 == s0) { mn = 0.f; mx = 0.f; }
    int t = j / FI, f = j % FI;
    float* a = d_agg + (size_t)n * (T_TOW * 4 * FI) + t * (4 * FI);
    a[f]          = mean;
    a[FI + f]     = mn;
    a[2 * FI + f] = mx;
    a[3 * FI + f] = stdv;
}

// ---------------- OUT[n,4875] build -----------------------------------------
__global__ void k_out() {
    int n = blockIdx.x;
    float cnt = (float)(d_rowstart[n + 1] - d_rowstart[n]);
    float log_deg = logf(fmaxf(cnt, 1.f) + 1.f);
    float amp = log_deg / AVG_DEG_LOG;
    float att = AVG_DEG_LOG / log_deg;
    const float* hrow = d_h + n * FI;
    const float* arow = d_agg + (size_t)n * 1500;
    float* o = d_outbuf + (size_t)n * HC_K;
    for (int idx = threadIdx.x; idx < HC_K; idx += 256) {
        int t = idx / OUT_DIM, c = idx % OUT_DIM;
        float v;
        if (c < FI) v = hrow[c];
        else {
            int c2 = c - FI;
            int blk = c2 / 300, kk = c2 % 300;
            v = arow[t * 300 + kk];
            if (blk == 1) v *= amp;
            else if (blk == 2) v *= att;
        }
        o[idx] = v;
    }
}

// ---------------- hc GEMM: [10000,4875] @ fusedW[4875,75] -------------------
__global__ void __launch_bounds__(256) k_gemm_hc() {
    const int BM = 128, BN = 64, BK = 64;
    const int KMAX = 4928;   // 77*64
    __shared__ float As[BM][BK + 4];
    __shared__ float Bs[BK][BN + 8];
    int bx = blockIdx.x, by = blockIdx.y;
    int tid = threadIdx.x;
    int row0 = by * BM, col0 = bx * BN;
    int lane = tid & 31, warp = tid >> 5;
    int wm = (warp >> 1) * 32, wn = (warp & 1) * 32;
    int g = lane >> 2, tc = lane & 3;

    float acc[2][4][4];
    #pragma unroll
    for (int i = 0; i < 2; i++)
        #pragma unroll
        for (int j = 0; j < 4; j++)
            #pragma unroll
            for (int q = 0; q < 4; q++) acc[i][j][q] = 0.f;

    int arow = tid >> 1;
    int ac0 = (tid & 1) * 32;
    int grow = row0 + arow;
    const float* ar = d_outbuf + (size_t)grow * HC_K;
    bool rok = grow < N_NODES;
    int bkr = tid >> 2, bc0 = (tid & 3) * 16;

    for (int k0 = 0; k0 < KMAX; k0 += BK) {
        #pragma unroll
        for (int c = 0; c < 32; c++) {
            int gc = k0 + ac0 + c;
            float v = (rok && gc < HC_K) ? ar[gc] : 0.f;
            As[arow][ac0 + c] = tf32r(v);
        }
        #pragma unroll
        for (int c = 0; c < 16; c++) {
            int kk = k0 + bkr, j = col0 + bc0 + c;
            float v = (kk < HC_K && j < FI) ? d_fusedW[(size_t)kk * FI + j] : 0.f;
            Bs[bkr][bc0 + c] = tf32r(v);
        }
        __syncthreads();
        #pragma unroll
        for (int kk = 0; kk < BK; kk += 8) {
            uint32_t a[2][4], b[4][2];
            #pragma unroll
            for (int i = 0; i < 2; i++) {
                int m = wm + i * 16 + g;
                a[i][0] = __float_as_uint(As[m][kk + tc]);
                a[i][1] = __float_as_uint(As[m + 8][kk + tc]);
                a[i][2] = __float_as_uint(As[m][kk + tc + 4]);
                a[i][3] = __float_as_uint(As[m + 8][kk + tc + 4]);
            }
            #pragma unroll
            for (int j = 0; j < 4; j++) {
                int n = wn + j * 8 + g;
                b[j][0] = __float_as_uint(Bs[kk + tc][n]);
                b[j][1] = __float_as_uint(Bs[kk + tc + 4][n]);
            }
            #pragma unroll
            for (int i = 0; i < 2; i++)
                #pragma unroll
                for (int j = 0; j < 4; j++) mma_tf32(acc[i][j], a[i], b[j]);
        }
        __syncthreads();
    }
    #pragma unroll
    for (int i = 0; i < 2; i++) {
        int r = row0 + wm + i * 16 + g;
        #pragma unroll
        for (int j = 0; j < 4; j++) {
            int cb = col0 + wn + j * 8 + 2 * tc;
            if (cb < FI) {
                if (r < N_NODES) {
                    d_hc[r * FI + cb] = acc[i][j][0] + d_bias2[cb];
                    if (cb + 1 < FI) d_hc[r * FI + cb + 1] = acc[i][j][1] + d_bias2[cb + 1];
                }
                if (r + 8 < N_NODES) {
                    d_hc[(r + 8) * FI + cb] = acc[i][j][2] + d_bias2[cb];
                    if (cb + 1 < FI) d_hc[(r + 8) * FI + cb + 1] = acc[i][j][3] + d_bias2[cb + 1];
                }
            }
        }
    }
}

// ---------------- BN stats (two-stage) + BN apply ----------------------------
__global__ void k_bnstats() {
    __shared__ float ssum[FI], ssq[FI];
    int tid = threadIdx.x;
    if (tid < FI) { ssum[tid] = 0.f; ssq[tid] = 0.f; }
    __syncthreads();
    int base = blockIdx.x * 100;
    for (int idx = tid; idx < 100 * FI; idx += blockDim.x) {
        int n = base + idx / FI, f = idx % FI;
        float v = d_hc[n * FI + f];
        atomicAdd(&ssum[f], v);
        atomicAdd(&ssq[f], v * v);
    }
    __syncthreads();
    if (tid < FI) {
        atomicAdd(&d_bnsum[tid], ssum[tid]);
        atomicAdd(&d_bnsq[tid], ssq[tid]);
    }
}

__global__ void k_bn(const float* __restrict__ g, const float* __restrict__ b) {
    int idx = blockIdx.x * blockDim.x + threadIdx.x;
    if (idx >= N_NODES * FI) return;
    int f = idx % FI;
    float mu = d_bnsum[f] / (float)N_NODES;
    float var = d_bnsq[f] / (float)N_NODES - mu * mu;
    float v = (d_hc[idx] - mu) * rsqrtf(var + 1e-5f) * g[f] + b[f];
    d_h[idx] = fmaxf(v, 0.f);
}

// ---------------- pool + MLP -------------------------------------------------
__global__ void k_poolzero() {
    int i = blockIdx.x * blockDim.x + threadIdx.x;
    if (i < N_GRAPHS * FI) d_pool[i] = 0.f;
}

__global__ void k_pool(const int* __restrict__ batch) {
    int idx = blockIdx.x * blockDim.x + threadIdx.x;
    if (idx >= N_NODES * FI) return;
    int n = idx / FI, f = idx % FI;
    atomicAdd(&d_pool[batch[n] * FI + f], d_h[idx]);
}

__global__ void k_mlp(const float* __restrict__ W1, const float* __restrict__ b1,
                      const float* __restrict__ W2, const float* __restrict__ b2,
                      const float* __restrict__ W3, const float* __restrict__ b3,
                      float* __restrict__ out) {
    __shared__ float g[FI], h1[50], h2[25];
    int gi = blockIdx.x;
    int tid = threadIdx.x;
    if (tid < FI) g[tid] = d_pool[gi * FI + tid];
    __syncthreads();
    if (tid < 50) {
        float a = b1[tid];
        for (int c = 0; c < FI; c++) a += g[c] * W1[c * 50 + tid];
        h1[tid] = fmaxf(a, 0.f);
    }
    __syncthreads();
    if (tid < 25) {
        float a = b2[tid];
        for (int c = 0; c < 50; c++) a += h1[c] * W2[c * 25 + tid];
        h2[tid] = fmaxf(a, 0.f);
    }
    __syncthreads();
    if (tid == 0) {
        float a = b3[0];
        for (int c = 0; c < 25; c++) a += h2[c] * W3[c];
        out[gi] = a;
    }
}

// ---------------- launch ------------------------------------------------------
extern "C" void kernel_launch(void* const* d_in, const int* in_sizes, int n_in,
                              void* d_out, int out_size) {
    const int*   x          = (const int*)d_in[0];
    const int*   edge_index = (const int*)d_in[1];
    const int*   edge_attr  = (const int*)d_in[2];
    const int*   batch      = (const int*)d_in[3];
    const float* node_emb   = (const float*)d_in[4];
    const float* edge_emb   = (const float*)d_in[5];
    const float* pre_lin_W  = (const float*)d_in[6];
    const float* pre_lin_b  = (const float*)d_in[7];
    const float* edge_enc_W = (const float*)d_in[8];
    const float* edge_enc_b = (const float*)d_in[9];
    const float* pre_W      = (const float*)d_in[10];
    const float* pre_b      = (const float*)d_in[11];
    const float* post_W     = (const float*)d_in[12];
    const float* post_b     = (const float*)d_in[13];
    const float* lin_W      = (const float*)d_in[14];
    const float* lin_b      = (const float*)d_in[15];
    const float* bn_g       = (const float*)d_in[16];
    const float* bn_b       = (const float*)d_in[17];
    const float* mlp_W1     = (const float*)d_in[18];
    const float* mlp_b1     = (const float*)d_in[19];
    const float* mlp_W2     = (const float*)d_in[20];
    const float* mlp_b2     = (const float*)d_in[21];
    const float* mlp_W3     = (const float*)d_in[22];
    const float* mlp_b3     = (const float*)d_in[23];
    float* out = (float*)d_out;

    k_h0<<<(N_NODES * FI + 255) / 256, 256>>>(x, node_emb, pre_lin_W, pre_lin_b);

    k_zero_cnt<<<(N_NODES + 255) / 256, 256>>>();
    k_count<<<(N_EDGES + 255) / 256, 256>>>(edge_index);
    k_scan<<<1, 1024>>>();
    k_fill<<<(N_EDGES + 255) / 256, 256>>>(edge_index, edge_attr);

    for (int l = 0; l < N_LAYERS; l++) {
        k_enctab<<<(16 * FI + 255) / 256, 256>>>(edge_emb,
            edge_enc_W + l * 50 * FI, edge_enc_b + l * FI);
        k_transpose<<<(MIN_DIM * MSG_DIM + 255) / 256, 256>>>(
            pre_W + (size_t)l * T_TOW * MIN_DIM * FI);
        k_fusew<<<(HC_K * FI + 255) / 256, 256>>>(
            post_W + (size_t)l * T_TOW * OUT_DIM * FO,
            lin_W + l * T_TOW * FO * FI);
        k_bias2<<<1, 128>>>(post_b + l * T_TOW * FO,
                            lin_W + l * T_TOW * FO * FI, lin_b + l * FI);
        k_bnzero<<<1, 128>>>();

        k_gemm_msg<<<dim3((MSG_DIM + 63) / 64, N_EDGES / 128), 256>>>(pre_b + l * MSG_DIM);
        k_agg<<<N_NODES, 384>>>();
        k_out<<<N_NODES, 256>>>();
        k_gemm_hc<<<dim3(2, (N_NODES + 127) / 128), 256>>>();
        k_bnstats<<<N_NODES / 100, 256>>>();
        k_bn<<<(N_NODES * FI + 255) / 256, 256>>>(bn_g + l * FI, bn_b + l * FI);
    }

    k_poolzero<<<(N_GRAPHS * FI + 255) / 256, 256>>>();
    k_pool<<<(N_NODES * FI + 255) / 256, 256>>>(batch);
    k_mlp<<<N_GRAPHS, 128>>>(mlp_W1, mlp_b1, mlp_W2, mlp_b2, mlp_W3, mlp_b3, out);
}

// round 3
// speedup vs baseline: 2.4911x; 2.4911x over previous
#include <cuda_runtime.h>
#include <math.h>
#include <stdint.h>

#define N_NODES 10000
#define N_EDGES 160000
#define N_GRAPHS 64
#define T_TOW 5
#define FI 75
#define FO 15
#define N_LAYERS 4
#define MSG_DIM 375        // T*FI
#define MIN_DIM 225        // 3*FI
#define OUT_DIM 975        // 13*FI
#define POST_DIM 75        // T*FO
#define AVG_DEG_LOG 2.8332133440562162f

// ---------------- scratch ----------------------------------------------------
__device__ float d_h[N_NODES * FI];
__device__ float d_hc[N_NODES * FI];
__device__ float d_msgs[N_EDGES * MSG_DIM];        // msgs in CSR edge order
__device__ float d_agg[N_NODES * T_TOW * 4 * FI];  // [N,T,300]
__device__ float d_Wt[MIN_DIM * MSG_DIM];          // pre_W[l] transposed [225,375]
__device__ float d_enctab[16 * FI];
__device__ int   d_cnt[N_NODES];
__device__ int   d_rowstart[N_NODES + 1];
__device__ int   d_cursor[N_NODES];
__device__ int   d_src_csr[N_EDGES];
__device__ int   d_dst_csr[N_EDGES];
__device__ int   d_combo_csr[N_EDGES];
__device__ float d_bnsum[FI];
__device__ float d_bnsq[FI];
__device__ float d_pool[N_GRAPHS * FI];

__device__ __forceinline__ float tf32r(float v) {
    uint32_t o;
    asm("cvt.rna.tf32.f32 %0, %1;" : "=r"(o) : "f"(v));
    return __uint_as_float(o);
}

__device__ __forceinline__ void mma_tf32(float* c, const uint32_t* a, const uint32_t* b) {
    asm volatile(
        "mma.sync.aligned.m16n8k8.row.col.f32.tf32.tf32.f32 "
        "{%0,%1,%2,%3}, {%4,%5,%6,%7}, {%8,%9}, {%0,%1,%2,%3};"
        : "+f"(c[0]), "+f"(c[1]), "+f"(c[2]), "+f"(c[3])
        : "r"(a[0]), "r"(a[1]), "r"(a[2]), "r"(a[3]), "r"(b[0]), "r"(b[1]));
}

// ---------------- h0 ----------------------------------------------------------
__global__ void k_h0(const int* __restrict__ x, const float* __restrict__ node_emb,
                     const float* __restrict__ W, const float* __restrict__ b) {
    int idx = blockIdx.x * blockDim.x + threadIdx.x;
    if (idx >= N_NODES * FI) return;
    int n = idx / FI, f = idx % FI;
    int i0 = x[n * 2 + 0], i1 = x[n * 2 + 1];
    const float* e0 = node_emb + i0 * FI;
    const float* e1 = node_emb + i1 * FI;
    float acc = b[f];
    #pragma unroll 5
    for (int c = 0; c < FI; c++) acc += e0[c] * W[c * FI + f];
    #pragma unroll 5
    for (int c = 0; c < FI; c++) acc += e1[c] * W[(FI + c) * FI + f];
    d_h[idx] = acc;
}

// ---------------- CSR build ---------------------------------------------------
__global__ void k_zero_cnt() {
    int i = blockIdx.x * blockDim.x + threadIdx.x;
    if (i < N_NODES) d_cnt[i] = 0;
}

__global__ void k_count(const int* __restrict__ edge_index) {
    int e = blockIdx.x * blockDim.x + threadIdx.x;
    if (e >= N_EDGES) return;
    atomicAdd(&d_cnt[edge_index[N_EDGES + e]], 1);
}

__global__ void k_scan() {
    __shared__ int ssum[1024];
    int tid = threadIdx.x;
    const int ITEMS = 10;
    int base = tid * ITEMS;
    int local[ITEMS];
    int s = 0;
    #pragma unroll
    for (int i = 0; i < ITEMS; i++) {
        int g = base + i;
        int v = (g < N_NODES) ? d_cnt[g] : 0;
        local[i] = s;
        s += v;
    }
    ssum[tid] = s;
    __syncthreads();
    for (int off = 1; off < 1024; off <<= 1) {
        int v = (tid >= off) ? ssum[tid - off] : 0;
        __syncthreads();
        ssum[tid] += v;
        __syncthreads();
    }
    int excl = (tid == 0) ? 0 : ssum[tid - 1];
    #pragma unroll
    for (int i = 0; i < ITEMS; i++) {
        int g = base + i;
        if (g < N_NODES) {
            int rs = excl + local[i];
            d_rowstart[g] = rs;
            d_cursor[g]   = rs;
        }
    }
    if (tid == 0) d_rowstart[N_NODES] = ssum[1023];
}

__global__ void k_fill(const int* __restrict__ edge_index, const int* __restrict__ edge_attr) {
    int e = blockIdx.x * blockDim.x + threadIdx.x;
    if (e >= N_EDGES) return;
    int dst = edge_index[N_EDGES + e];
    int pos = atomicAdd(&d_cursor[dst], 1);
    d_src_csr[pos]   = edge_index[e];
    d_dst_csr[pos]   = dst;
    d_combo_csr[pos] = edge_attr[e * 2] * 4 + edge_attr[e * 2 + 1];
}

// ---------------- per-layer prep ------------------------------------------------
__global__ void k_enctab(const float* __restrict__ edge_emb,
                         const float* __restrict__ encW, const float* __restrict__ encb) {
    int idx = blockIdx.x * blockDim.x + threadIdx.x;
    if (idx >= 16 * FI) return;
    int combo = idx / FI, f = idx % FI;
    int a0 = combo >> 2, a1 = combo & 3;
    const float* e0 = edge_emb + a0 * 25;
    const float* e1 = edge_emb + a1 * 25;
    float acc = encb[f];
    #pragma unroll 5
    for (int q = 0; q < 25; q++) acc += e0[q] * encW[q * FI + f];
    #pragma unroll 5
    for (int q = 0; q < 25; q++) acc += e1[q] * encW[(25 + q) * FI + f];
    d_enctab[idx] = acc;
}

__global__ void k_transpose(const float* __restrict__ preW) {
    int idx = blockIdx.x * blockDim.x + threadIdx.x;
    if (idx >= MIN_DIM * MSG_DIM) return;
    int c = idx / MSG_DIM, j = idx % MSG_DIM;
    int t = j / FI, f = j % FI;
    d_Wt[idx] = preW[(t * MIN_DIM + c) * FI + f];
}

__global__ void k_bnzero() {
    int i = threadIdx.x;
    if (i < FI) { d_bnsum[i] = 0.f; d_bnsq[i] = 0.f; }
}

// ---------------- msg GEMM: tf32 mma, fused gather, CSR order -------------------
// C[160000,375] = [h[dst] | h[src] | enc(combo)] @ Wt[225,375] + bias
// BM=128, BN=128, K = 3 segments of 75 (padded to 80 in smem)
__global__ void __launch_bounds__(256, 2) k_gemm_msg(const float* __restrict__ bias) {
    const int BM = 128, BN = 128;
    const int AS = 84, BS = 136;             // padded strides (conflict-free)
    __shared__ float As[BM * AS];            // 128x84  (43KB)
    __shared__ float Bs[80 * BS];            // 80x136  (43.5KB)
    __shared__ int s_off[3][BM];             // node base offsets per segment

    int tid = threadIdx.x;
    int row0 = blockIdx.y * BM;
    int col0 = blockIdx.x * BN;
    int lane = tid & 31, warp = tid >> 5;
    int wm = (warp >> 2) * 64;               // 2 warp-rows
    int wn = (warp & 3) * 32;                // 4 warp-cols
    int g = lane >> 2, tc = lane & 3;

    if (tid < BM) {
        int r = row0 + tid;
        s_off[0][tid] = d_dst_csr[r] * FI;
        s_off[1][tid] = d_src_csr[r] * FI;
        s_off[2][tid] = d_combo_csr[r] * FI;
    }

    float acc[4][4][4];
    #pragma unroll
    for (int i = 0; i < 4; i++)
        #pragma unroll
        for (int j = 0; j < 4; j++)
            #pragma unroll
            for (int q = 0; q < 4; q++) acc[i][j][q] = 0.f;

    __syncthreads();

    for (int seg = 0; seg < 3; seg++) {
        const float* abase = (seg < 2) ? d_h : d_enctab;
        const int* offarr = s_off[seg];
        // A fill: 128 rows x 80 cols, coalesced along columns
        #pragma unroll
        for (int i = 0; i < 40; i++) {
            int idx = i * 256 + tid;
            int r = idx / 80, c = idx - r * 80;
            float v = (c < FI) ? abase[offarr[r] + c] : 0.f;
            As[r * AS + c] = tf32r(v);
        }
        // B fill: 80 x 128
        #pragma unroll
        for (int i = 0; i < 40; i++) {
            int idx = i * 256 + tid;
            int kr = idx >> 7, c = idx & 127;
            int j = col0 + c;
            float v = (kr < FI && j < MSG_DIM) ? d_Wt[(seg * FI + kr) * MSG_DIM + j] : 0.f;
            Bs[kr * BS + c] = tf32r(v);
        }
        __syncthreads();
        #pragma unroll
        for (int kk = 0; kk < 80; kk += 8) {
            uint32_t a[4][4], b[4][2];
            #pragma unroll
            for (int i = 0; i < 4; i++) {
                int m = wm + i * 16 + g;
                a[i][0] = __float_as_uint(As[m * AS + kk + tc]);
                a[i][1] = __float_as_uint(As[(m + 8) * AS + kk + tc]);
                a[i][2] = __float_as_uint(As[m * AS + kk + tc + 4]);
                a[i][3] = __float_as_uint(As[(m + 8) * AS + kk + tc + 4]);
            }
            #pragma unroll
            for (int j = 0; j < 4; j++) {
                int n = wn + j * 8 + g;
                b[j][0] = __float_as_uint(Bs[(kk + tc) * BS + n]);
                b[j][1] = __float_as_uint(Bs[(kk + tc + 4) * BS + n]);
            }
            #pragma unroll
            for (int i = 0; i < 4; i++)
                #pragma unroll
                for (int j = 0; j < 4; j++) mma_tf32(acc[i][j], a[i], b[j]);
        }
        __syncthreads();
    }

    // epilogue: rows always in-bounds (160000 % 128 == 0)
    #pragma unroll
    for (int i = 0; i < 4; i++) {
        int r = row0 + wm + i * 16 + g;
        #pragma unroll
        for (int j = 0; j < 4; j++) {
            int cb = col0 + wn + j * 8 + 2 * tc;
            if (cb < MSG_DIM) {
                float b0 = bias[cb];
                d_msgs[(size_t)r * MSG_DIM + cb] = acc[i][j][0] + b0;
                d_msgs[(size_t)(r + 8) * MSG_DIM + cb] = acc[i][j][2] + b0;
                if (cb + 1 < MSG_DIM) {
                    float b1 = bias[cb + 1];
                    d_msgs[(size_t)r * MSG_DIM + cb + 1] = acc[i][j][1] + b1;
                    d_msgs[(size_t)(r + 8) * MSG_DIM + cb + 1] = acc[i][j][3] + b1;
                }
            }
        }
    }
}

// ---------------- segment reduce (msgs in CSR order) ----------------------------
__global__ void k_agg() {
    int n = blockIdx.x;
    int j = threadIdx.x;
    if (j >= MSG_DIM) return;
    int s0 = d_rowstart[n], s1 = d_rowstart[n + 1];
    float s = 0.f, sq = 0.f, mn = 3.4e38f, mx = -3.4e38f;
    for (int i = s0; i < s1; i++) {
        float v = d_msgs[(size_t)i * MSG_DIM + j];
        s += v; sq += v * v;
        mn = fminf(mn, v); mx = fmaxf(mx, v);
    }
    float cnt = (float)(s1 - s0);
    float deg = fmaxf(cnt, 1.f);
    float mean = s / deg;
    float var = sq / deg - mean * mean;
    if (var < 0.f) var = 0.f;
    float stdv = sqrtf(var + 1e-5f);
    if (s1 == s0) { mn = 0.f; mx = 0.f; }
    int t = j / FI, f = j % FI;
    float* a = d_agg + (size_t)n * (T_TOW * 4 * FI) + t * (4 * FI);
    a[f]          = mean;
    a[FI + f]     = mn;
    a[2 * FI + f] = mx;
    a[3 * FI + f] = stdv;
}

// ---------------- per-node post-tower GEMM + lin -> hc ---------------------------
__global__ void k_post(const float* __restrict__ postW, const float* __restrict__ postb,
                       const float* __restrict__ linW,  const float* __restrict__ linb) {
    __shared__ float outs[T_TOW * OUT_DIM];
    __shared__ float posts[POST_DIM];
    int n = blockIdx.x;
    int tid = threadIdx.x;
    float cnt = (float)(d_rowstart[n + 1] - d_rowstart[n]);
    float log_deg = logf(fmaxf(cnt, 1.f) + 1.f);
    float amp = log_deg / AVG_DEG_LOG;
    float att = AVG_DEG_LOG / log_deg;
    const float* hrow = d_h + n * FI;
    const float* arow = d_agg + (size_t)n * (T_TOW * 4 * FI);
    for (int idx = tid; idx < T_TOW * OUT_DIM; idx += 128) {
        int t = idx / OUT_DIM, c = idx % OUT_DIM;
        float v;
        if (c < FI) v = hrow[c];
        else {
            int c2 = c - FI;
            int blk = c2 / 300, kk = c2 % 300;
            v = arow[t * 300 + kk];
            if (blk == 1) v *= amp;
            else if (blk == 2) v *= att;
        }
        outs[idx] = v;
    }
    __syncthreads();
    if (tid < POST_DIM) {
        int t = tid / FO, f = tid % FO;
        float acc = postb[t * FO + f];
        const float* w = postW + (size_t)t * OUT_DIM * FO + f;
        const float* o = outs + t * OUT_DIM;
        for (int c = 0; c < OUT_DIM; c++) acc += o[c] * w[c * FO];
        posts[tid] = acc;
    }
    __syncthreads();
    if (tid < FI) {
        float acc = linb[tid];
        #pragma unroll 5
        for (int j = 0; j < POST_DIM; j++) acc += posts[j] * linW[j * FI + tid];
        d_hc[n * FI + tid] = acc;
    }
}

// ---------------- BN stats (two-stage) + BN apply --------------------------------
__global__ void k_bnstats() {
    __shared__ float ssum[FI], ssq[FI];
    int tid = threadIdx.x;
    if (tid < FI) { ssum[tid] = 0.f; ssq[tid] = 0.f; }
    __syncthreads();
    int base = blockIdx.x * 100;
    for (int idx = tid; idx < 100 * FI; idx += blockDim.x) {
        int n = base + idx / FI, f = idx % FI;
        float v = d_hc[n * FI + f];
        atomicAdd(&ssum[f], v);
        atomicAdd(&ssq[f], v * v);
    }
    __syncthreads();
    if (tid < FI) {
        atomicAdd(&d_bnsum[tid], ssum[tid]);
        atomicAdd(&d_bnsq[tid], ssq[tid]);
    }
}

__global__ void k_bn(const float* __restrict__ g, const float* __restrict__ b) {
    int idx = blockIdx.x * blockDim.x + threadIdx.x;
    if (idx >= N_NODES * FI) return;
    int f = idx % FI;
    float mu = d_bnsum[f] / (float)N_NODES;
    float var = d_bnsq[f] / (float)N_NODES - mu * mu;
    float v = (d_hc[idx] - mu) * rsqrtf(var + 1e-5f) * g[f] + b[f];
    d_h[idx] = fmaxf(v, 0.f);
}

// ---------------- pool + MLP -----------------------------------------------------
__global__ void k_poolzero() {
    int i = blockIdx.x * blockDim.x + threadIdx.x;
    if (i < N_GRAPHS * FI) d_pool[i] = 0.f;
}

__global__ void k_pool(const int* __restrict__ batch) {
    int idx = blockIdx.x * blockDim.x + threadIdx.x;
    if (idx >= N_NODES * FI) return;
    int n = idx / FI, f = idx % FI;
    atomicAdd(&d_pool[batch[n] * FI + f], d_h[idx]);
}

__global__ void k_mlp(const float* __restrict__ W1, const float* __restrict__ b1,
                      const float* __restrict__ W2, const float* __restrict__ b2,
                      const float* __restrict__ W3, const float* __restrict__ b3,
                      float* __restrict__ out) {
    __shared__ float g[FI], h1[50], h2[25];
    int gi = blockIdx.x;
    int tid = threadIdx.x;
    if (tid < FI) g[tid] = d_pool[gi * FI + tid];
    __syncthreads();
    if (tid < 50) {
        float a = b1[tid];
        for (int c = 0; c < FI; c++) a += g[c] * W1[c * 50 + tid];
        h1[tid] = fmaxf(a, 0.f);
    }
    __syncthreads();
    if (tid < 25) {
        float a = b2[tid];
        for (int c = 0; c < 50; c++) a += h1[c] * W2[c * 25 + tid];
        h2[tid] = fmaxf(a, 0.f);
    }
    __syncthreads();
    if (tid == 0) {
        float a = b3[0];
        for (int c = 0; c < 25; c++) a += h2[c] * W3[c];
        out[gi] = a;
    }
}

// ---------------- launch -----------------------------------------------------------
extern "C" void kernel_launch(void* const* d_in, const int* in_sizes, int n_in,
                              void* d_out, int out_size) {
    const int*   x          = (const int*)d_in[0];
    const int*   edge_index = (const int*)d_in[1];
    const int*   edge_attr  = (const int*)d_in[2];
    const int*   batch      = (const int*)d_in[3];
    const float* node_emb   = (const float*)d_in[4];
    const float* edge_emb   = (const float*)d_in[5];
    const float* pre_lin_W  = (const float*)d_in[6];
    const float* pre_lin_b  = (const float*)d_in[7];
    const float* edge_enc_W = (const float*)d_in[8];
    const float* edge_enc_b = (const float*)d_in[9];
    const float* pre_W      = (const float*)d_in[10];
    const float* pre_b      = (const float*)d_in[11];
    const float* post_W     = (const float*)d_in[12];
    const float* post_b     = (const float*)d_in[13];
    const float* lin_W      = (const float*)d_in[14];
    const float* lin_b      = (const float*)d_in[15];
    const float* bn_g       = (const float*)d_in[16];
    const float* bn_b       = (const float*)d_in[17];
    const float* mlp_W1     = (const float*)d_in[18];
    const float* mlp_b1     = (const float*)d_in[19];
    const float* mlp_W2     = (const float*)d_in[20];
    const float* mlp_b2     = (const float*)d_in[21];
    const float* mlp_W3     = (const float*)d_in[22];
    const float* mlp_b3     = (const float*)d_in[23];
    float* out = (float*)d_out;

    k_h0<<<(N_NODES * FI + 255) / 256, 256>>>(x, node_emb, pre_lin_W, pre_lin_b);

    k_zero_cnt<<<(N_NODES + 255) / 256, 256>>>();
    k_count<<<(N_EDGES + 255) / 256, 256>>>(edge_index);
    k_scan<<<1, 1024>>>();
    k_fill<<<(N_EDGES + 255) / 256, 256>>>(edge_index, edge_attr);

    for (int l = 0; l < N_LAYERS; l++) {
        k_enctab<<<(16 * FI + 255) / 256, 256>>>(edge_emb,
            edge_enc_W + l * 50 * FI, edge_enc_b + l * FI);
        k_transpose<<<(MIN_DIM * MSG_DIM + 255) / 256, 256>>>(
            pre_W + (size_t)l * T_TOW * MIN_DIM * FI);
        k_bnzero<<<1, 128>>>();

        k_gemm_msg<<<dim3(3, N_EDGES / 128), 256>>>(pre_b + l * MSG_DIM);
        k_agg<<<N_NODES, 384>>>();
        k_post<<<N_NODES, 128>>>(post_W + (size_t)l * T_TOW * OUT_DIM * FO,
                                 post_b + l * POST_DIM,
                                 lin_W + l * POST_DIM * FI,
                                 lin_b + l * FI);
        k_bnstats<<<N_NODES / 100, 256>>>();
        k_bn<<<(N_NODES * FI + 255) / 256, 256>>>(bn_g + l * FI, bn_b + l * FI);
    }

    k_poolzero<<<(N_GRAPHS * FI + 255) / 256, 256>>>();
    k_pool<<<(N_NODES * FI + 255) / 256, 256>>>(batch);
    k_mlp<<<N_GRAPHS, 128>>>(mlp_W1, mlp_b1, mlp_W2, mlp_b2, mlp_W3, mlp_b3, out);
}